// round 1
// baseline (speedup 1.0000x reference)
#include <cuda_runtime.h>
#include <cuda_bf16.h>
#include <cstdint>

// Problem constants (fixed by reference: B=256, C=512, H=W=14, D=32, A=2000)
#define BB   256
#define CC   512
#define HW   196
#define HW4  49          // 196/4 float4 per row
#define ND   32
#define NA   2000

// Scratch (no allocations allowed in kernel_launch)
__device__ float g_att[BB * CC];       // attended [B][C]
__device__ int   g_blist[ND * BB];     // per-expert sample lists
__device__ int   g_bcnt[ND];           // per-expert counts

// ---------------------------------------------------------------------------
// Kernel 0: bucket samples by expert. Deterministic: each of 32 threads scans
// the instance array in fixed order and builds its own expert's list.
// ---------------------------------------------------------------------------
__global__ void bucket_kernel(const int* __restrict__ instance) {
    __shared__ int sinst[BB];
    if (threadIdx.x < BB) sinst[threadIdx.x] = instance[threadIdx.x];
    __syncthreads();
    if (threadIdx.x < ND) {
        int d = threadIdx.x;
        int cnt = 0;
        #pragma unroll 4
        for (int b = 0; b < BB; b++) {
            if (sinst[b] == d) g_blist[d * BB + cnt++] = b;
        }
        g_bcnt[d] = cnt;
    }
}

// ---------------------------------------------------------------------------
// Kernel 1: attended[b][c] = (1/196) * sum_hw mask[b][hw] * feat[b][c][hw]
// One warp per (b,c) row. Rows are 784 B = 49 float4 (16B-aligned).
// ---------------------------------------------------------------------------
__global__ void attend_kernel(const float4* __restrict__ feat,
                              const float4* __restrict__ mask) {
    int w    = (blockIdx.x * blockDim.x + threadIdx.x) >> 5;   // global warp = b*512+c
    int lane = threadIdx.x & 31;
    int b    = w >> 9;

    const float4* f = feat + (size_t)w * HW4;
    const float4* m = mask + (size_t)b * HW4;

    float4 v0 = f[lane];
    float4 m0 = m[lane];
    float s = v0.x * m0.x + v0.y * m0.y + v0.z * m0.z + v0.w * m0.w;
    if (lane < HW4 - 32) {                 // lanes 0..16 take the tail 17 float4
        float4 v1 = f[lane + 32];
        float4 m1 = m[lane + 32];
        s += v1.x * m1.x + v1.y * m1.y + v1.z * m1.z + v1.w * m1.w;
    }
    #pragma unroll
    for (int off = 16; off > 0; off >>= 1)
        s += __shfl_xor_sync(0xffffffffu, s, off);
    if (lane == 0)
        g_att[w] = s * (1.0f / (float)HW);
}

// ---------------------------------------------------------------------------
// Kernel 2: per-expert batched matvec.
//   grid = (A_TILES=8, experts=32, ZSLICES=8), block = 128 threads.
//   Each block: one expert d, one tile of 256 answers, chunk-slice z.
//   Chunks of 4 samples: attended rows staged in smem (8 KB), each thread
//   accumulates 4 samples x 2 answers; weight read once per chunk
//   (float2, coalesced). Deterministic: c-loop order fixed per (sample,answer).
// ---------------------------------------------------------------------------
#define S2_THREADS 128
#define S2_APT     2                 // answers per thread (float2)
#define A_TILE     (S2_THREADS * S2_APT)   // 256
#define A_TILES    8                 // ceil(2000/256)
#define CHUNK      4
#define ZSLICES    8

__global__ __launch_bounds__(S2_THREADS)
void expert_mv_kernel(const float* __restrict__ weight,
                      const float* __restrict__ bias,
                      float* __restrict__ out) {
    const int d = blockIdx.y;
    const int cnt = g_bcnt[d];
    const int nchunks = (cnt + CHUNK - 1) / CHUNK;
    const int z = blockIdx.z;

    __shared__ float satt[CHUNK * CC];   // 4 x 512 floats = 8 KB

    const int a0 = blockIdx.x * A_TILE + threadIdx.x * S2_APT;
    const bool a_ok = (a0 < NA);         // a0 even, NA even -> a0+1 also valid
    const float* wp = weight + (size_t)d * CC * NA + a0;

    for (int ch = z; ch < nchunks; ch += ZSLICES) {
        const int s0 = ch * CHUNK;
        const int ns = min(CHUNK, cnt - s0);

        int bidx[CHUNK];
        #pragma unroll
        for (int i = 0; i < CHUNK; i++)
            bidx[i] = g_blist[d * BB + min(s0 + i, cnt - 1)];

        // stage attended rows for this chunk into smem (coalesced)
        __syncthreads();   // protect smem from previous iteration's readers
        for (int t = threadIdx.x; t < CHUNK * CC; t += S2_THREADS) {
            int s = t >> 9;        // /512
            int c = t & (CC - 1);
            satt[t] = g_att[bidx[s] * CC + c];
        }
        __syncthreads();

        float2 acc0 = {0.f, 0.f}, acc1 = {0.f, 0.f};
        float2 acc2 = {0.f, 0.f}, acc3 = {0.f, 0.f};

        if (a_ok) {
            #pragma unroll 4
            for (int c = 0; c < CC; c++) {
                float2 wv = *reinterpret_cast<const float2*>(wp + (size_t)c * NA);
                float m0 = satt[0 * CC + c];
                float m1 = satt[1 * CC + c];
                float m2 = satt[2 * CC + c];
                float m3 = satt[3 * CC + c];
                acc0.x += m0 * wv.x;  acc0.y += m0 * wv.y;
                acc1.x += m1 * wv.x;  acc1.y += m1 * wv.y;
                acc2.x += m2 * wv.x;  acc2.y += m2 * wv.y;
                acc3.x += m3 * wv.x;  acc3.y += m3 * wv.y;
            }
            float bx = bias[(size_t)d * NA + a0];
            float by = bias[(size_t)d * NA + a0 + 1];
            float2 r[CHUNK] = {acc0, acc1, acc2, acc3};
            #pragma unroll
            for (int i = 0; i < CHUNK; i++) {
                if (i < ns) {
                    float* o = out + (size_t)bidx[i] * NA + a0;
                    o[0] = r[i].x + bx;
                    o[1] = r[i].y + by;
                }
            }
        }
    }
}

// ---------------------------------------------------------------------------
// Launch: metadata order = mask, features, weight, bias, instance; out = f32.
// ---------------------------------------------------------------------------
extern "C" void kernel_launch(void* const* d_in, const int* in_sizes, int n_in,
                              void* d_out, int out_size) {
    const float* mask     = (const float*)d_in[0];   // [256,1,14,14]
    const float* features = (const float*)d_in[1];   // [256,512,14,14]
    const float* weight   = (const float*)d_in[2];   // [32,512,2000]
    const float* bias     = (const float*)d_in[3];   // [32,2000]
    const int*   instance = (const int*)d_in[4];     // [256]
    float*       out      = (float*)d_out;           // [256,2000]

    bucket_kernel<<<1, 256>>>(instance);

    // one warp per (b,c): 256*512 warps, 8 warps/block
    attend_kernel<<<(BB * CC) / 8, 256>>>(
        reinterpret_cast<const float4*>(features),
        reinterpret_cast<const float4*>(mask));

    dim3 grid(A_TILES, ND, ZSLICES);
    expert_mv_kernel<<<grid, S2_THREADS>>>(weight, bias, out);
}